// round 10
// baseline (speedup 1.0000x reference)
#include <cuda_runtime.h>
#include <cstdint>

// SinusoidPositionEncoding: out[b,s,:] = sum_m x[b,s,m] * pe[m,:]
// x one-hot over m (4096). Early-exit chunked scan (~56% x-traffic, confirmed
// R4-R9). R10: FOUR rows interleaved per warp -> 16 LDG.128 (8KB) in flight per
// round-trip per warp. Rate has tracked loads-in-flight/warp across all rounds
// (4->4.96, 8->5.28 TB/s); this doubles it again. Blocks 128 thr, grid 1024
// (~1.4 waves, backfill preserved). No atomics, no single-wave schedule.
// x (8,2048,4096) f32, pe (4096,128) f32, out (8,2048,128) f32.

#define N_ROWS (8 * 2048)   // 16384
#define M_VEC  1024         // 4096/4 float4 per row
#define D_VEC  32           // 128/4
#define CHUNK_LOADS 4       // 4 x LDG.128 per lane per chunk = 512 floats
#define N_CHUNKS 8
#define R_PER_WARP 4
#define WARPS_PER_BLOCK 4   // 128 threads
#define ROWS_PER_BLOCK (WARPS_PER_BLOCK * R_PER_WARP)   // 16

__device__ __forceinline__ void gather_pe(const float4* __restrict__ pe,
                                          unsigned mask, int hitpos, uint4 hitv,
                                          int lane, float4& acc) {
    while (mask) {
        const int src = __ffs(mask) - 1;
        mask &= mask - 1;
        const int   p  = __shfl_sync(0xffffffffu, hitpos, src);
        const float vx = __uint_as_float(__shfl_sync(0xffffffffu, hitv.x, src));
        const float vy = __uint_as_float(__shfl_sync(0xffffffffu, hitv.y, src));
        const float vz = __uint_as_float(__shfl_sync(0xffffffffu, hitv.z, src));
        const float vw = __uint_as_float(__shfl_sync(0xffffffffu, hitv.w, src));
        const int e = p * 4;
        if (__float_as_uint(vx) != 0u) {
            const float4 pr = __ldg(&pe[(size_t)(e + 0) * D_VEC + lane]);
            acc.x += vx * pr.x; acc.y += vx * pr.y; acc.z += vx * pr.z; acc.w += vx * pr.w;
        }
        if (__float_as_uint(vy) != 0u) {
            const float4 pr = __ldg(&pe[(size_t)(e + 1) * D_VEC + lane]);
            acc.x += vy * pr.x; acc.y += vy * pr.y; acc.z += vy * pr.z; acc.w += vy * pr.w;
        }
        if (__float_as_uint(vz) != 0u) {
            const float4 pr = __ldg(&pe[(size_t)(e + 2) * D_VEC + lane]);
            acc.x += vz * pr.x; acc.y += vz * pr.y; acc.z += vz * pr.z; acc.w += vz * pr.w;
        }
        if (__float_as_uint(vw) != 0u) {
            const float4 pr = __ldg(&pe[(size_t)(e + 3) * D_VEC + lane]);
            acc.x += vw * pr.x; acc.y += vw * pr.y; acc.z += vw * pr.z; acc.w += vw * pr.w;
        }
    }
}

__global__ __launch_bounds__(128)
void pe_onehot_gather4_kernel(const uint4* __restrict__ x,
                              const float4* __restrict__ pe,
                              float4* __restrict__ out) {
    const int warp = threadIdx.x >> 5;
    const int lane = threadIdx.x & 31;
    // Block owns 16 contiguous rows; warp w owns rows base+w+4*r, r=0..3.
    const int row0 = blockIdx.x * ROWS_PER_BLOCK + warp;

    const uint4* xr[R_PER_WARP];
    #pragma unroll
    for (int r = 0; r < R_PER_WARP; r++)
        xr[r] = x + (size_t)(row0 + 4 * r) * M_VEC;

    uint4 hv[R_PER_WARP];
    int hp[R_PER_WARP];
    unsigned ball[R_PER_WARP];
    #pragma unroll
    for (int r = 0; r < R_PER_WARP; r++) {
        hv[r] = make_uint4(0u, 0u, 0u, 0u);
        hp[r] = -1;
        ball[r] = 0u;
    }

    for (int c = 0; c < N_CHUNKS; c++) {
        const int base = c * (CHUNK_LOADS * 32);
        bool act[R_PER_WARP];
        #pragma unroll
        for (int r = 0; r < R_PER_WARP; r++) act[r] = (ball[r] == 0u);  // warp-uniform

        // ---- issue ALL loads for all active rows first (front-batched) ----
        uint4 v[R_PER_WARP][CHUNK_LOADS];
        #pragma unroll
        for (int r = 0; r < R_PER_WARP; r++) {
            if (act[r]) {
                #pragma unroll
                for (int j = 0; j < CHUNK_LOADS; j++)
                    v[r][j] = __ldcs(&xr[r][base + j * 32 + lane]);
            }
        }

        // ---- then check + ballot per row ----
        #pragma unroll
        for (int r = 0; r < R_PER_WARP; r++) {
            if (act[r]) {
                #pragma unroll
                for (int j = 0; j < CHUNK_LOADS; j++)
                    if ((v[r][j].x | v[r][j].y | v[r][j].z | v[r][j].w) != 0u) {
                        hv[r] = v[r][j];
                        hp[r] = base + j * 32 + lane;
                    }
                ball[r] = __ballot_sync(0xffffffffu, hp[r] >= 0);
            }
        }

        if (ball[0] && ball[1] && ball[2] && ball[3]) break;
    }

    #pragma unroll
    for (int r = 0; r < R_PER_WARP; r++) {
        float4 acc = make_float4(0.f, 0.f, 0.f, 0.f);
        gather_pe(pe, ball[r], hp[r], hv[r], lane, acc);
        __stcs(&out[(size_t)(row0 + 4 * r) * D_VEC + lane], acc);
    }
}

extern "C" void kernel_launch(void* const* d_in, const int* in_sizes, int n_in,
                              void* d_out, int out_size) {
    const uint4*  x  = (const uint4*)d_in[0];    // (8,2048,4096) f32
    const float4* pe = (const float4*)d_in[1];   // (4096,128)    f32
    float4* out = (float4*)d_out;                // (8,2048,128)  f32

    const int grid = N_ROWS / ROWS_PER_BLOCK;    // 1024 blocks of 128 threads
    pe_onehot_gather4_kernel<<<grid, 128>>>(x, pe, out);
}

// round 11
// speedup vs baseline: 1.0381x; 1.0381x over previous
#include <cuda_runtime.h>
#include <cstdint>

// SinusoidPositionEncoding: out[b,s,:] = sum_m x[b,s,m] * pe[m,:]
// x one-hot over m (4096). Early-exit scan, 2 rows/warp (R9 trunk, 29.6us,
// 5.31 TB/s). R11: depth-2 software pipeline over 256-float chunks:
// chunk c+1 is in flight while chunk c is checked, chunk c+2 issues before
// c+1 is checked -> continuous issue (2 chunks per DRAM round-trip) instead
// of one serialized chunk per round-trip. Overshoot = 1 chunk/row (+4% bytes).
// x (8,2048,4096) f32, pe (4096,128) f32, out (8,2048,128) f32.

#define N_ROWS (8 * 2048)   // 16384
#define M_VEC  1024         // 4096/4 float4 per row
#define D_VEC  32           // 128/4
#define CL 2                // loads per chunk per lane (256 floats/chunk)
#define CHUNK_V (CL * 32)   // 64 float4 per chunk
#define N_CHUNKS 16         // 16 * 256 = 4096
#define WARPS_PER_BLOCK 4   // 128 threads
#define ROWS_PER_BLOCK (WARPS_PER_BLOCK * 2)   // 8

__device__ __forceinline__ void gather_pe(const float4* __restrict__ pe,
                                          unsigned mask, int hitpos, uint4 hitv,
                                          int lane, float4& acc) {
    while (mask) {
        const int src = __ffs(mask) - 1;
        mask &= mask - 1;
        const int   p  = __shfl_sync(0xffffffffu, hitpos, src);
        const float vx = __uint_as_float(__shfl_sync(0xffffffffu, hitv.x, src));
        const float vy = __uint_as_float(__shfl_sync(0xffffffffu, hitv.y, src));
        const float vz = __uint_as_float(__shfl_sync(0xffffffffu, hitv.z, src));
        const float vw = __uint_as_float(__shfl_sync(0xffffffffu, hitv.w, src));
        const int e = p * 4;
        if (__float_as_uint(vx) != 0u) {
            const float4 pr = __ldg(&pe[(size_t)(e + 0) * D_VEC + lane]);
            acc.x += vx * pr.x; acc.y += vx * pr.y; acc.z += vx * pr.z; acc.w += vx * pr.w;
        }
        if (__float_as_uint(vy) != 0u) {
            const float4 pr = __ldg(&pe[(size_t)(e + 1) * D_VEC + lane]);
            acc.x += vy * pr.x; acc.y += vy * pr.y; acc.z += vy * pr.z; acc.w += vy * pr.w;
        }
        if (__float_as_uint(vz) != 0u) {
            const float4 pr = __ldg(&pe[(size_t)(e + 2) * D_VEC + lane]);
            acc.x += vz * pr.x; acc.y += vz * pr.y; acc.z += vz * pr.z; acc.w += vz * pr.w;
        }
        if (__float_as_uint(vw) != 0u) {
            const float4 pr = __ldg(&pe[(size_t)(e + 3) * D_VEC + lane]);
            acc.x += vw * pr.x; acc.y += vw * pr.y; acc.z += vw * pr.z; acc.w += vw * pr.w;
        }
    }
}

// Check one buffered chunk for nonzeros; update hit state + ballot.
#define CHECK_CHUNK(BUF, CIDX, hv, hp, ball)                                   \
    do {                                                                       \
        _Pragma("unroll")                                                      \
        for (int j = 0; j < CL; j++)                                           \
            if (((BUF)[j].x | (BUF)[j].y | (BUF)[j].z | (BUF)[j].w) != 0u) {   \
                (hv) = (BUF)[j];                                               \
                (hp) = (CIDX) * CHUNK_V + j * 32 + lane;                       \
            }                                                                  \
        (ball) = __ballot_sync(0xffffffffu, (hp) >= 0);                        \
    } while (0)

#define LOAD_CHUNK(BUF, XPTR, CIDX)                                            \
    do {                                                                       \
        _Pragma("unroll")                                                      \
        for (int j = 0; j < CL; j++)                                           \
            (BUF)[j] = __ldcs(&(XPTR)[(CIDX) * CHUNK_V + j * 32 + lane]);      \
    } while (0)

__global__ __launch_bounds__(128)
void pe_onehot_pipe_kernel(const uint4* __restrict__ x,
                           const float4* __restrict__ pe,
                           float4* __restrict__ out) {
    const int warp = threadIdx.x >> 5;
    const int lane = threadIdx.x & 31;
    // Block owns 8 contiguous rows; warp w owns rows base+w and base+w+4.
    const int rowA = blockIdx.x * ROWS_PER_BLOCK + warp;
    const int rowB = rowA + WARPS_PER_BLOCK;

    const uint4* xA = x + (size_t)rowA * M_VEC;
    const uint4* xB = x + (size_t)rowB * M_VEC;

    uint4 bA0[CL], bA1[CL], bB0[CL], bB1[CL];
    uint4 hvA = make_uint4(0u,0u,0u,0u), hvB = make_uint4(0u,0u,0u,0u);
    int hpA = -1, hpB = -1;
    unsigned ballA = 0u, ballB = 0u;

    // Prologue: chunk 0 into buffer 0 for both rows.
    LOAD_CHUNK(bA0, xA, 0);
    LOAD_CHUNK(bB0, xB, 0);

    for (int it = 0; it < N_CHUNKS / 2; it++) {
        const int c0 = 2 * it;

        // Issue chunk c0+1 (buffer 1) while chunk c0 is in flight / arriving.
        if (ballA == 0u) LOAD_CHUNK(bA1, xA, c0 + 1);
        if (ballB == 0u) LOAD_CHUNK(bB1, xB, c0 + 1);

        // Check chunk c0 (buffer 0).
        if (ballA == 0u) CHECK_CHUNK(bA0, c0, hvA, hpA, ballA);
        if (ballB == 0u) CHECK_CHUNK(bB0, c0, hvB, hpB, ballB);

        // Issue chunk c0+2 (buffer 0) before checking c0+1.
        if (it < N_CHUNKS / 2 - 1) {
            if (ballA == 0u) LOAD_CHUNK(bA0, xA, c0 + 2);
            if (ballB == 0u) LOAD_CHUNK(bB0, xB, c0 + 2);
        }

        // Check chunk c0+1 (buffer 1).
        if (ballA == 0u) CHECK_CHUNK(bA1, c0 + 1, hvA, hpA, ballA);
        if (ballB == 0u) CHECK_CHUNK(bB1, c0 + 1, hvB, hpB, ballB);

        if (ballA && ballB) break;
    }

    float4 accA = make_float4(0.f,0.f,0.f,0.f);
    float4 accB = make_float4(0.f,0.f,0.f,0.f);
    gather_pe(pe, ballA, hpA, hvA, lane, accA);
    gather_pe(pe, ballB, hpB, hvB, lane, accB);

    __stcs(&out[(size_t)rowA * D_VEC + lane], accA);
    __stcs(&out[(size_t)rowB * D_VEC + lane], accB);
}

extern "C" void kernel_launch(void* const* d_in, const int* in_sizes, int n_in,
                              void* d_out, int out_size) {
    const uint4*  x  = (const uint4*)d_in[0];    // (8,2048,4096) f32
    const float4* pe = (const float4*)d_in[1];   // (4096,128)    f32
    float4* out = (float4*)d_out;                // (8,2048,128)  f32

    const int grid = N_ROWS / ROWS_PER_BLOCK;    // 2048 blocks of 128 threads
    pe_onehot_pipe_kernel<<<grid, 128>>>(x, pe, out);
}

// round 12
// speedup vs baseline: 1.1038x; 1.0633x over previous
#include <cuda_runtime.h>
#include <cstdint>

// SinusoidPositionEncoding: out[b,s,:] = sum_m x[b,s,m] * pe[m,:]
// x one-hot over m (4096). Early-exit prefix scan. Empirics R4-R11: rate
// plateaus at ~5.3 TB/s whenever >=8 LDG.128/warp are in flight; pipelining
// trades rate for overshoot bytes ~1:1. So: ride the plateau, minimize bytes.
// R12: 4 rows per warp x 2-load chunks (256-float check granularity) =
// 8 loads in flight (keeps 5.3) with expected read 8.5KB/row (vs R9's 9KB).
// Rows contiguous per warp for DRAM-page locality. regs ~75 (CL=2, unlike
// R10's CL=4/96-reg failure). x (8,2048,4096) f32, pe (4096,128) f32,
// out (8,2048,128) f32.

#define N_ROWS (8 * 2048)   // 16384
#define M_VEC  1024         // 4096/4 float4 per row
#define D_VEC  32           // 128/4
#define CL 2                // loads per chunk per lane (256 floats/chunk)
#define CHUNK_V (CL * 32)   // 64 float4 per chunk
#define N_CHUNKS 16         // 16 * 256 = 4096
#define R_PER_WARP 4
#define WARPS_PER_BLOCK 4   // 128 threads
#define ROWS_PER_BLOCK (WARPS_PER_BLOCK * R_PER_WARP)   // 16

__device__ __forceinline__ void gather_pe(const float4* __restrict__ pe,
                                          unsigned mask, int hitpos, uint4 hitv,
                                          int lane, float4& acc) {
    while (mask) {
        const int src = __ffs(mask) - 1;
        mask &= mask - 1;
        const int   p  = __shfl_sync(0xffffffffu, hitpos, src);
        const float vx = __uint_as_float(__shfl_sync(0xffffffffu, hitv.x, src));
        const float vy = __uint_as_float(__shfl_sync(0xffffffffu, hitv.y, src));
        const float vz = __uint_as_float(__shfl_sync(0xffffffffu, hitv.z, src));
        const float vw = __uint_as_float(__shfl_sync(0xffffffffu, hitv.w, src));
        const int e = p * 4;
        if (__float_as_uint(vx) != 0u) {
            const float4 pr = __ldg(&pe[(size_t)(e + 0) * D_VEC + lane]);
            acc.x += vx * pr.x; acc.y += vx * pr.y; acc.z += vx * pr.z; acc.w += vx * pr.w;
        }
        if (__float_as_uint(vy) != 0u) {
            const float4 pr = __ldg(&pe[(size_t)(e + 1) * D_VEC + lane]);
            acc.x += vy * pr.x; acc.y += vy * pr.y; acc.z += vy * pr.z; acc.w += vy * pr.w;
        }
        if (__float_as_uint(vz) != 0u) {
            const float4 pr = __ldg(&pe[(size_t)(e + 2) * D_VEC + lane]);
            acc.x += vz * pr.x; acc.y += vz * pr.y; acc.z += vz * pr.z; acc.w += vz * pr.w;
        }
        if (__float_as_uint(vw) != 0u) {
            const float4 pr = __ldg(&pe[(size_t)(e + 3) * D_VEC + lane]);
            acc.x += vw * pr.x; acc.y += vw * pr.y; acc.z += vw * pr.z; acc.w += vw * pr.w;
        }
    }
}

__global__ __launch_bounds__(128)
void pe_onehot_g4f_kernel(const uint4* __restrict__ x,
                          const float4* __restrict__ pe,
                          float4* __restrict__ out) {
    const int warp = threadIdx.x >> 5;
    const int lane = threadIdx.x & 31;
    // Warp owns 4 contiguous rows; block covers 16 contiguous rows.
    const int row0 = blockIdx.x * ROWS_PER_BLOCK + warp * R_PER_WARP;

    const uint4* xr[R_PER_WARP];
    #pragma unroll
    for (int r = 0; r < R_PER_WARP; r++)
        xr[r] = x + (size_t)(row0 + r) * M_VEC;

    uint4 hv[R_PER_WARP];
    int hp[R_PER_WARP];
    unsigned ball[R_PER_WARP];
    #pragma unroll
    for (int r = 0; r < R_PER_WARP; r++) {
        hv[r] = make_uint4(0u, 0u, 0u, 0u);
        hp[r] = -1;
        ball[r] = 0u;
    }

    for (int c = 0; c < N_CHUNKS; c++) {
        const int base = c * CHUNK_V;
        bool act[R_PER_WARP];
        #pragma unroll
        for (int r = 0; r < R_PER_WARP; r++) act[r] = (ball[r] == 0u);  // warp-uniform

        // ---- issue ALL loads for all active rows first (front-batched) ----
        uint4 v[R_PER_WARP][CL];
        #pragma unroll
        for (int r = 0; r < R_PER_WARP; r++) {
            if (act[r]) {
                #pragma unroll
                for (int j = 0; j < CL; j++)
                    v[r][j] = __ldcs(&xr[r][base + j * 32 + lane]);
            }
        }

        // ---- then check + ballot per row ----
        #pragma unroll
        for (int r = 0; r < R_PER_WARP; r++) {
            if (act[r]) {
                #pragma unroll
                for (int j = 0; j < CL; j++)
                    if ((v[r][j].x | v[r][j].y | v[r][j].z | v[r][j].w) != 0u) {
                        hv[r] = v[r][j];
                        hp[r] = base + j * 32 + lane;
                    }
                ball[r] = __ballot_sync(0xffffffffu, hp[r] >= 0);
            }
        }

        if (ball[0] && ball[1] && ball[2] && ball[3]) break;
    }

    #pragma unroll
    for (int r = 0; r < R_PER_WARP; r++) {
        float4 acc = make_float4(0.f, 0.f, 0.f, 0.f);
        gather_pe(pe, ball[r], hp[r], hv[r], lane, acc);
        __stcs(&out[(size_t)(row0 + r) * D_VEC + lane], acc);
    }
}

extern "C" void kernel_launch(void* const* d_in, const int* in_sizes, int n_in,
                              void* d_out, int out_size) {
    const uint4*  x  = (const uint4*)d_in[0];    // (8,2048,4096) f32
    const float4* pe = (const float4*)d_in[1];   // (4096,128)    f32
    float4* out = (float4*)d_out;                // (8,2048,128)  f32

    const int grid = N_ROWS / ROWS_PER_BLOCK;    // 1024 blocks of 128 threads
    pe_onehot_g4f_kernel<<<grid, 128>>>(x, pe, out);
}